// round 10
// baseline (speedup 1.0000x reference)
#include <cuda_runtime.h>
#include <cuda_fp16.h>
#include <cstdint>

#define N_USERS 30000
#define N_ENT   70000
#define N_NODES 100000
#define N_EDGES 1600000

#define SCAN_BS 512
#define SCAN_NB ((N_NODES + SCAN_BS - 1) / SCAN_BS)   // 196

typedef unsigned long long ull;

// Scratch
__device__ float4  g_egoA[N_NODES * 16];     // layer-0 ego fp32
__device__ float2  g_egoB[N_NODES * 32];     // layer-1 ego fp32
__device__ __half2 g_egoAh[N_NODES * 32];    // fp16 shadows (gather only)
__device__ __half2 g_egoBh[N_NODES * 32];
__device__ int  g_cnt[N_NODES];
__device__ int  g_off[N_NODES + 1];
__device__ int  g_cur[N_NODES];
__device__ ull  g_state[SCAN_NB];            // lookback: (status<<32)|value
__device__ int2 g_edges[N_EDGES];            // row-sorted (col, half2(v,v) bits)
__device__ float2 g_pack1[64 * 64];          // (W1_1[k][j], W2_1[k][j])
__device__ float2 g_pack2[64 * 32];          // (W1_2[k][j], W2_2[k][j])

// ---- f32x2 packed helpers -------------------------------------------------
__device__ __forceinline__ ull pack2(float a, float b) {
    ull r; asm("mov.b64 %0, {%1, %2};" : "=l"(r) : "f"(a), "f"(b)); return r;
}
__device__ __forceinline__ void unpack2(ull p, float& a, float& b) {
    asm("mov.b64 {%0, %1}, %2;" : "=f"(a), "=f"(b) : "l"(p));
}
__device__ __forceinline__ void fma2(ull& d, ull a, ull b) {
    asm("fma.rn.f32x2 %0, %1, %2, %0;" : "+l"(d) : "l"(a), "l"(b));
}
__device__ __forceinline__ __half2 h2bits(int b) {
    __half2 h; *(int*)&h = b; return h;
}

// ---------------------------------------------------------------------------
// k_init: ego0 (fp32 + fp16 shadow), out[:,0:64], edge histogram, weight pack.
// ---------------------------------------------------------------------------
__global__ __launch_bounds__(256) void k_init(
    const float4* __restrict__ user4,
    const float4* __restrict__ ent4,
    const int* __restrict__ rows,
    const float* __restrict__ W1_1, const float* __restrict__ W2_1,
    const float* __restrict__ W1_2, const float* __restrict__ W2_2,
    float4* __restrict__ out4)
{
    int idx = blockIdx.x * blockDim.x + threadIdx.x;
    if (idx < N_EDGES) atomicAdd(&g_cnt[rows[idx]], 1);
    if (idx < 64 * 64) g_pack1[idx] = make_float2(W1_1[idx], W2_1[idx]);
    else if (idx < 64 * 64 + 64 * 32) {
        int t = idx - 64 * 64;
        g_pack2[t] = make_float2(W1_2[t], W2_2[t]);
    }
    if (idx >= N_NODES * 16) return;
    int row = idx >> 4;
    int part = idx & 15;
    float4 v = (row < N_USERS) ? user4[row * 16 + part]
                               : ent4[(row - N_USERS) * 16 + part];
    g_egoA[idx] = v;
    g_egoAh[row * 32 + 2 * part]     = __floats2half2_rn(v.x, v.y);
    g_egoAh[row * 32 + 2 * part + 1] = __floats2half2_rn(v.z, v.w);
    out4[row * 40 + part] = v;
}

// ---------------------------------------------------------------------------
// Single-pass exclusive scan of g_cnt (decoupled lookback).
// ---------------------------------------------------------------------------
__global__ __launch_bounds__(SCAN_BS) void k_scan()
{
    __shared__ int warp_sums[16];
    __shared__ int blk_prefix;

    int tid = threadIdx.x;
    int bid = blockIdx.x;
    int lane = tid & 31;
    int wid = tid >> 5;
    int i = bid * SCAN_BS + tid;
    int v = (i < N_NODES) ? g_cnt[i] : 0;

    int x = v;
    #pragma unroll
    for (int off = 1; off < 32; off <<= 1) {
        int t = __shfl_up_sync(0xFFFFFFFFu, x, off);
        if (lane >= off) x += t;
    }
    if (lane == 31) warp_sums[wid] = x;
    __syncthreads();
    if (wid == 0) {
        int s = (lane < 16) ? warp_sums[lane] : 0;
        #pragma unroll
        for (int off = 1; off < 16; off <<= 1) {
            int t = __shfl_up_sync(0xFFFFFFFFu, s, off);
            if (lane >= off) s += t;
        }
        if (lane < 16) warp_sums[lane] = s;
    }
    __syncthreads();
    int incl = x + (wid > 0 ? warp_sums[wid - 1] : 0);
    int block_total = warp_sums[15];

    if (tid == 0) {
        if (bid == 0) {
            atomicExch(&g_state[0], (2ULL << 32) | (unsigned)block_total);
            blk_prefix = 0;
        } else {
            atomicExch(&g_state[bid], (1ULL << 32) | (unsigned)block_total);
            int pref = 0;
            int j = bid - 1;
            while (true) {
                ull s = atomicAdd(&g_state[j], 0ULL);
                unsigned st = (unsigned)(s >> 32);
                if (st == 2) { pref += (int)(unsigned)s; break; }
                if (st == 1) { pref += (int)(unsigned)s; j--; }
            }
            atomicExch(&g_state[bid], (2ULL << 32) | (unsigned)(pref + block_total));
            blk_prefix = pref;
        }
    }
    __syncthreads();

    int excl = blk_prefix + incl - v;
    if (i < N_NODES) { g_off[i] = excl; g_cur[i] = excl; }
    if (i == N_NODES - 1) g_off[N_NODES] = N_EDGES;
}

__global__ __launch_bounds__(256) void k_scatter(
    const int* __restrict__ rows,
    const int* __restrict__ cols,
    const float* __restrict__ vals)
{
    int e = blockIdx.x * blockDim.x + threadIdx.x;
    if (e >= N_EDGES) return;
    int pos = atomicAdd(&g_cur[rows[e]], 1);
    float v = vals[e];
    __half2 vv = __floats2half2_rn(v, v);
    g_edges[pos] = make_int2(cols[e], *(const int*)&vv);
}

// ---------------------------------------------------------------------------
// Gather: side += val * egoH[col] over edges [s, e).
// Software-pipelined: next 4-edge group's descriptors (2x int4) load while the
// current group's gathers are in flight. fp16 accumulation per 4-edge group.
// ---------------------------------------------------------------------------
__device__ __forceinline__ void gather_quad(
    const __half2* __restrict__ egoH, int lane, int4 c0, int4 c1,
    float& ax, float& ay)
{
    __half2 x0 = egoH[c0.x * 32 + lane];
    __half2 x1 = egoH[c0.z * 32 + lane];
    __half2 x2 = egoH[c1.x * 32 + lane];
    __half2 x3 = egoH[c1.z * 32 + lane];
    __half2 acc = __hmul2(h2bits(c0.y), x0);
    acc = __hfma2(h2bits(c0.w), x1, acc);
    acc = __hfma2(h2bits(c1.y), x2, acc);
    acc = __hfma2(h2bits(c1.w), x3, acc);
    float2 f = __half22float2(acc);
    ax += f.x; ay += f.y;
}

__device__ __forceinline__ void gather_row(
    const __half2* __restrict__ egoH, int lane, int s, int e,
    float& ax, float& ay)
{
    int i = s;
    if ((i & 1) && i < e) {
        int2 cv = g_edges[i];
        __half2 p = __hmul2(h2bits(cv.y), egoH[cv.x * 32 + lane]);
        float2 f = __half22float2(p);
        ax += f.x; ay += f.y;
        i++;
    }
    int n4 = (e - i) >> 2;          // number of full 4-edge groups
    if (n4 > 0) {
        const int4* ep = (const int4*)g_edges;
        int q = i >> 1;
        int4 c0 = ep[q];
        int4 c1 = ep[q + 1];
        for (int g = 1; g < n4; g++) {
            int4 n0 = ep[q + 2 * g];        // prefetch next group
            int4 n1 = ep[q + 2 * g + 1];
            gather_quad(egoH, lane, c0, c1, ax, ay);
            c0 = n0; c1 = n1;
        }
        gather_quad(egoH, lane, c0, c1, ax, ay);
        i += n4 * 4;
    }
    for (; i < e; i++) {
        int2 cv = g_edges[i];
        __half2 p = __hmul2(h2bits(cv.y), egoH[cv.x * 32 + lane]);
        float2 f = __half22float2(p);
        ax += f.x; ay += f.y;
    }
}

// ---------------------------------------------------------------------------
// Fused layer 1: CSR spmm (pipelined fp16 gather) + bi-interaction 64->64
// (FFMA2, weights via L1-resident __ldg) + l2norm. One warp: 4 rows.
// ---------------------------------------------------------------------------
__global__ __launch_bounds__(256, 5) void k_layer1(
    const float* __restrict__ b1, const float* __restrict__ b2,
    float* __restrict__ out)
{
    __shared__ float2 am[8][4][64];   // [warp][row][k] = (ego+side, ego*side)

    int tid = threadIdx.x;
    int warp = tid >> 5;
    int lane = tid & 31;
    int j0 = 2 * lane;
    int rbase = (blockIdx.x * 8 + warp) * 4;

    const float2* egoA2 = (const float2*)g_egoA;

    // batched CSR offsets: one coalesced load + shfl
    int oidx = rbase + min(lane, 4);
    if (oidx > N_NODES) oidx = N_NODES;
    int off_l = g_off[oidx];

    #pragma unroll
    for (int rr = 0; rr < 4; rr++) {
        int r = rbase + rr;
        if (r >= N_NODES) break;
        int s = __shfl_sync(0xFFFFFFFFu, off_l, rr);
        int e = __shfl_sync(0xFFFFFFFFu, off_l, rr + 1);
        float ax = 0.f, ay = 0.f;
        gather_row(g_egoAh, lane, s, e, ax, ay);
        float2 eg = egoA2[r * 32 + lane];
        am[warp][rr][2 * lane]     = make_float2(eg.x + ax, eg.x * ax);
        am[warp][rr][2 * lane + 1] = make_float2(eg.y + ay, eg.y * ay);
    }
    __syncwarp();

    ull bias0 = pack2(b1[j0], b2[j0]);
    ull bias1 = pack2(b1[j0 + 1], b2[j0 + 1]);
    ull acc[4][2];
    #pragma unroll
    for (int rr = 0; rr < 4; rr++) { acc[rr][0] = bias0; acc[rr][1] = bias1; }

    const float4* Wp = (const float4*)g_pack1;   // [k*32+lane] = (W1,W2)[j0],(W1,W2)[j1]
    #pragma unroll 4
    for (int k2 = 0; k2 < 32; k2++) {
        float4 wa = __ldg(&Wp[(2 * k2) * 32 + lane]);
        float4 wb = __ldg(&Wp[(2 * k2 + 1) * 32 + lane]);
        ull wax = pack2(wa.x, wa.y), way = pack2(wa.z, wa.w);
        ull wbx = pack2(wb.x, wb.y), wby = pack2(wb.z, wb.w);
        #pragma unroll
        for (int rr = 0; rr < 4; rr++) {
            ulonglong2 amp = *(const ulonglong2*)&am[warp][rr][2 * k2];
            fma2(acc[rr][0], amp.x, wax);
            fma2(acc[rr][1], amp.x, way);
            fma2(acc[rr][0], amp.y, wbx);
            fma2(acc[rr][1], amp.y, wby);
        }
    }

    #pragma unroll
    for (int rr = 0; rr < 4; rr++) {
        int r = rbase + rr;
        if (r >= N_NODES) break;
        float s0, bb0, s1, bb1v;
        unpack2(acc[rr][0], s0, bb0);
        unpack2(acc[rr][1], s1, bb1v);
        float h0 = (s0 > 0.f ? s0 : 0.01f * s0) + (bb0 > 0.f ? bb0 : 0.01f * bb0);
        float h1 = (s1 > 0.f ? s1 : 0.01f * s1) + (bb1v > 0.f ? bb1v : 0.01f * bb1v);
        float ss = h0 * h0 + h1 * h1;
        #pragma unroll
        for (int off = 16; off > 0; off >>= 1)
            ss += __shfl_xor_sync(0xFFFFFFFFu, ss, off);
        float inv = 1.f / fmaxf(sqrtf(ss), 1e-12f);
        h0 *= inv; h1 *= inv;
        g_egoB[r * 32 + lane] = make_float2(h0, h1);
        g_egoBh[r * 32 + lane] = __floats2half2_rn(h0, h1);
        ((float2*)out)[r * 80 + 32 + lane] = make_float2(h0, h1);
    }
}

// ---------------------------------------------------------------------------
// Fused layer 2: CSR spmm (pipelined fp16 gather from ego1) + bi 64->32.
// ---------------------------------------------------------------------------
__global__ __launch_bounds__(256, 5) void k_layer2(
    const float* __restrict__ b1, const float* __restrict__ b2,
    float* __restrict__ out)
{
    __shared__ float2 am[8][4][64];

    int tid = threadIdx.x;
    int warp = tid >> 5;
    int lane = tid & 31;
    int rbase = (blockIdx.x * 8 + warp) * 4;

    int oidx = rbase + min(lane, 4);
    if (oidx > N_NODES) oidx = N_NODES;
    int off_l = g_off[oidx];

    #pragma unroll
    for (int rr = 0; rr < 4; rr++) {
        int r = rbase + rr;
        if (r >= N_NODES) break;
        int s = __shfl_sync(0xFFFFFFFFu, off_l, rr);
        int e = __shfl_sync(0xFFFFFFFFu, off_l, rr + 1);
        float ax = 0.f, ay = 0.f;
        gather_row(g_egoBh, lane, s, e, ax, ay);
        float2 eg = g_egoB[r * 32 + lane];
        am[warp][rr][2 * lane]     = make_float2(eg.x + ax, eg.x * ax);
        am[warp][rr][2 * lane + 1] = make_float2(eg.y + ay, eg.y * ay);
    }
    __syncwarp();

    ull bias = pack2(b1[lane], b2[lane]);
    ull acc[4];
    #pragma unroll
    for (int rr = 0; rr < 4; rr++) acc[rr] = bias;

    const float2* Wp = g_pack2;                  // [k*32+lane] = (W1,W2)[lane]
    #pragma unroll 4
    for (int k2 = 0; k2 < 32; k2++) {
        float2 wa = __ldg(&Wp[(2 * k2) * 32 + lane]);
        float2 wb = __ldg(&Wp[(2 * k2 + 1) * 32 + lane]);
        ull wap = pack2(wa.x, wa.y);
        ull wbp = pack2(wb.x, wb.y);
        #pragma unroll
        for (int rr = 0; rr < 4; rr++) {
            ulonglong2 amp = *(const ulonglong2*)&am[warp][rr][2 * k2];
            fma2(acc[rr], amp.x, wap);
            fma2(acc[rr], amp.y, wbp);
        }
    }

    #pragma unroll
    for (int rr = 0; rr < 4; rr++) {
        int r = rbase + rr;
        if (r >= N_NODES) break;
        float s, bb;
        unpack2(acc[rr], s, bb);
        float h = (s > 0.f ? s : 0.01f * s) + (bb > 0.f ? bb : 0.01f * bb);
        float ss = h * h;
        #pragma unroll
        for (int off = 16; off > 0; off >>= 1)
            ss += __shfl_xor_sync(0xFFFFFFFFu, ss, off);
        float inv = 1.f / fmaxf(sqrtf(ss), 1e-12f);
        out[r * 160 + 128 + lane] = h * inv;
    }
}

// ---------------------------------------------------------------------------
extern "C" void kernel_launch(void* const* d_in, const int* in_sizes, int n_in,
                              void* d_out, int out_size)
{
    const float* user_tab = (const float*)d_in[0];
    const float* entity_tab = (const float*)d_in[1];
    const float* A_vals = (const float*)d_in[2];
    const float* W1_1 = (const float*)d_in[3];
    const float* b1_1 = (const float*)d_in[4];
    const float* W2_1 = (const float*)d_in[5];
    const float* b2_1 = (const float*)d_in[6];
    const float* W1_2 = (const float*)d_in[7];
    const float* b1_2 = (const float*)d_in[8];
    const float* W2_2 = (const float*)d_in[9];
    const float* b2_2 = (const float*)d_in[10];
    const int* A_rows = (const int*)d_in[11];
    const int* A_cols = (const int*)d_in[12];
    float* out = (float*)d_out;

    int eg = (N_EDGES + 255) / 256;

    void* cnt_ptr = nullptr;
    cudaGetSymbolAddress(&cnt_ptr, g_cnt);
    cudaMemsetAsync(cnt_ptr, 0, N_NODES * sizeof(int));
    void* st_ptr = nullptr;
    cudaGetSymbolAddress(&st_ptr, g_state);
    cudaMemsetAsync(st_ptr, 0, SCAN_NB * sizeof(ull));

    // 0: init (ego + out[:,0:64] + histogram + weight pack)
    k_init<<<(N_NODES * 16 + 255) / 256, 256>>>(
        (const float4*)user_tab, (const float4*)entity_tab, A_rows,
        W1_1, W2_1, W1_2, W2_2, (float4*)out);
    // 1: single-pass scan
    k_scan<<<SCAN_NB, SCAN_BS>>>();
    // 2: scatter into row-sorted edge list (vals pre-converted to half2)
    k_scatter<<<eg, 256>>>(A_rows, A_cols, A_vals);
    // 3: fused layer 1  (profiled by ncu -s5 -c1)
    k_layer1<<<(N_NODES + 31) / 32, 256>>>(b1_1, b2_1, out);
    // 4: fused layer 2
    k_layer2<<<(N_NODES + 31) / 32, 256>>>(b1_2, b2_2, out);
}

// round 11
// speedup vs baseline: 1.1781x; 1.1781x over previous
#include <cuda_runtime.h>
#include <cuda_fp16.h>
#include <cstdint>

#define N_USERS 30000
#define N_NODES 100000
#define N_EDGES 1600000

#define SCAN_BS 512
#define SCAN_NB ((N_NODES + SCAN_BS - 1) / SCAN_BS)   // 196

typedef unsigned long long ull;

// Scratch
__device__ float4  g_egoA[N_NODES * 16];     // layer-0 ego fp32
__device__ float2  g_egoB[N_NODES * 32];     // layer-1 ego fp32
__device__ __half2 g_egoAh[N_NODES * 32];    // fp16 shadows (gather only)
__device__ __half2 g_egoBh[N_NODES * 32];
__device__ int  g_cnt[N_NODES];
__device__ int  g_off[N_NODES + 1];
__device__ int  g_cur[N_NODES];
__device__ ull  g_state[SCAN_NB];
__device__ int2 g_edges[N_EDGES];            // row-sorted (col, half2(v,v) bits)

__device__ __forceinline__ __half2 h2bits(int b) {
    __half2 h; *(int*)&h = b; return h;
}
__device__ __forceinline__ uint32_t smem_u32(const void* p) {
    return (uint32_t)__cvta_generic_to_shared(p);
}

#define LDSM_X4(r0, r1, r2, r3, addr) \
    asm volatile("ldmatrix.sync.aligned.m8n8.x4.shared.b16 {%0,%1,%2,%3}, [%4];" \
        : "=r"(r0), "=r"(r1), "=r"(r2), "=r"(r3) : "r"(addr))
#define LDSM_X2T(r0, r1, addr) \
    asm volatile("ldmatrix.sync.aligned.m8n8.x2.trans.shared.b16 {%0,%1}, [%2];" \
        : "=r"(r0), "=r"(r1) : "r"(addr))
#define MMA16816(d, a0, a1, a2, a3, b0, b1) \
    asm volatile("mma.sync.aligned.m16n8k16.row.col.f32.f16.f16.f32 " \
        "{%0,%1,%2,%3},{%4,%5,%6,%7},{%8,%9},{%0,%1,%2,%3};" \
        : "+f"((d)[0]), "+f"((d)[1]), "+f"((d)[2]), "+f"((d)[3]) \
        : "r"(a0), "r"(a1), "r"(a2), "r"(a3), "r"(b0), "r"(b1))

// ---------------------------------------------------------------------------
// k_init: ego0 (fp32 + fp16 shadow), out[:,0:64], edge histogram.
// ---------------------------------------------------------------------------
__global__ __launch_bounds__(256) void k_init(
    const float4* __restrict__ user4,
    const float4* __restrict__ ent4,
    const int* __restrict__ rows,
    float4* __restrict__ out4)
{
    int idx = blockIdx.x * blockDim.x + threadIdx.x;
    if (idx < N_EDGES) atomicAdd(&g_cnt[rows[idx]], 1);
    if (idx >= N_NODES * 16) return;
    int row = idx >> 4;
    int part = idx & 15;
    float4 v = (row < N_USERS) ? user4[row * 16 + part]
                               : ent4[(row - N_USERS) * 16 + part];
    g_egoA[idx] = v;
    g_egoAh[row * 32 + 2 * part]     = __floats2half2_rn(v.x, v.y);
    g_egoAh[row * 32 + 2 * part + 1] = __floats2half2_rn(v.z, v.w);
    out4[row * 40 + part] = v;
}

// ---------------------------------------------------------------------------
// Single-pass exclusive scan (decoupled lookback).
// ---------------------------------------------------------------------------
__global__ __launch_bounds__(SCAN_BS) void k_scan()
{
    __shared__ int warp_sums[16];
    __shared__ int blk_prefix;

    int tid = threadIdx.x;
    int bid = blockIdx.x;
    int lane = tid & 31;
    int wid = tid >> 5;
    int i = bid * SCAN_BS + tid;
    int v = (i < N_NODES) ? g_cnt[i] : 0;

    int x = v;
    #pragma unroll
    for (int off = 1; off < 32; off <<= 1) {
        int t = __shfl_up_sync(0xFFFFFFFFu, x, off);
        if (lane >= off) x += t;
    }
    if (lane == 31) warp_sums[wid] = x;
    __syncthreads();
    if (wid == 0) {
        int s = (lane < 16) ? warp_sums[lane] : 0;
        #pragma unroll
        for (int off = 1; off < 16; off <<= 1) {
            int t = __shfl_up_sync(0xFFFFFFFFu, s, off);
            if (lane >= off) s += t;
        }
        if (lane < 16) warp_sums[lane] = s;
    }
    __syncthreads();
    int incl = x + (wid > 0 ? warp_sums[wid - 1] : 0);
    int block_total = warp_sums[15];

    if (tid == 0) {
        if (bid == 0) {
            atomicExch(&g_state[0], (2ULL << 32) | (unsigned)block_total);
            blk_prefix = 0;
        } else {
            atomicExch(&g_state[bid], (1ULL << 32) | (unsigned)block_total);
            int pref = 0;
            int j = bid - 1;
            while (true) {
                ull s = atomicAdd(&g_state[j], 0ULL);
                unsigned st = (unsigned)(s >> 32);
                if (st == 2) { pref += (int)(unsigned)s; break; }
                if (st == 1) { pref += (int)(unsigned)s; j--; }
            }
            atomicExch(&g_state[bid], (2ULL << 32) | (unsigned)(pref + block_total));
            blk_prefix = pref;
        }
    }
    __syncthreads();

    int excl = blk_prefix + incl - v;
    if (i < N_NODES) { g_off[i] = excl; g_cur[i] = excl; }
    if (i == N_NODES - 1) g_off[N_NODES] = N_EDGES;
}

__global__ __launch_bounds__(256) void k_scatter(
    const int* __restrict__ rows,
    const int* __restrict__ cols,
    const float* __restrict__ vals)
{
    int e = blockIdx.x * blockDim.x + threadIdx.x;
    if (e >= N_EDGES) return;
    int pos = atomicAdd(&g_cur[rows[e]], 1);
    float v = vals[e];
    __half2 vv = __floats2half2_rn(v, v);
    g_edges[pos] = make_int2(cols[e], *(const int*)&vv);
}

// ---------------------------------------------------------------------------
// Gather: side += val * egoH[col] over edges [s, e). HFMA2, fp16 groups of 8.
// ---------------------------------------------------------------------------
__device__ __forceinline__ void gather_row(
    const __half2* __restrict__ egoH, int lane, int s, int e,
    float& ax, float& ay)
{
    int i = s;
    if ((i & 1) && i < e) {
        int2 cv = g_edges[i];
        __half2 p = __hmul2(h2bits(cv.y), egoH[cv.x * 32 + lane]);
        float2 f = __half22float2(p);
        ax += f.x; ay += f.y;
        i++;
    }
    const int4* ep = (const int4*)g_edges;
    for (; i + 7 < e; i += 8) {
        int4 p0 = ep[(i >> 1) + 0];
        int4 p1 = ep[(i >> 1) + 1];
        int4 p2 = ep[(i >> 1) + 2];
        int4 p3 = ep[(i >> 1) + 3];
        __half2 x0 = egoH[p0.x * 32 + lane];
        __half2 x1 = egoH[p0.z * 32 + lane];
        __half2 x2 = egoH[p1.x * 32 + lane];
        __half2 x3 = egoH[p1.z * 32 + lane];
        __half2 x4 = egoH[p2.x * 32 + lane];
        __half2 x5 = egoH[p2.z * 32 + lane];
        __half2 x6 = egoH[p3.x * 32 + lane];
        __half2 x7 = egoH[p3.z * 32 + lane];
        __half2 acc = __hmul2(h2bits(p0.y), x0);
        acc = __hfma2(h2bits(p0.w), x1, acc);
        acc = __hfma2(h2bits(p1.y), x2, acc);
        acc = __hfma2(h2bits(p1.w), x3, acc);
        acc = __hfma2(h2bits(p2.y), x4, acc);
        acc = __hfma2(h2bits(p2.w), x5, acc);
        acc = __hfma2(h2bits(p3.y), x6, acc);
        acc = __hfma2(h2bits(p3.w), x7, acc);
        float2 f = __half22float2(acc);
        ax += f.x; ay += f.y;
    }
    for (; i < e; i++) {
        int2 cv = g_edges[i];
        __half2 p = __hmul2(h2bits(cv.y), egoH[cv.x * 32 + lane]);
        float2 f = __half22float2(p);
        ax += f.x; ay += f.y;
    }
}

// ---------------------------------------------------------------------------
// Fused layer 1: gather (8 rows/warp) -> fp16 am tiles in smem -> mma.sync
// GEMMs [64,64]x[64,64] (x2) -> lrelu/sum/l2norm epilogue.
// Block = 256 threads = 64 rows. Warp (t=wid/2, h=wid&1) computes D[16, 32].
// ---------------------------------------------------------------------------
__global__ __launch_bounds__(256) void k_layer1(
    const float* __restrict__ W1, const float* __restrict__ b1,
    const float* __restrict__ W2, const float* __restrict__ b2,
    float* __restrict__ out)
{
    __shared__ __align__(16) __half sA[64 * 72];   // a = ego + side
    __shared__ __align__(16) __half sM[64 * 72];   // m = ego * side
    __shared__ __align__(16) __half sW1[64 * 72];
    __shared__ __align__(16) __half sW2[64 * 72];
    __shared__ float sP[64][2];

    int tid = threadIdx.x;
    int wid = tid >> 5;
    int lane = tid & 31;
    int rbase = blockIdx.x * 64;

    // weights -> fp16 smem (padded stride 72)
    for (int i = tid; i < 4096; i += 256) {
        int k = i >> 6, n = i & 63;
        sW1[k * 72 + n] = __float2half(W1[i]);
        sW2[k * 72 + n] = __float2half(W2[i]);
    }
    // last block: zero am tiles (rows beyond N_NODES stay benign)
    if (rbase + 64 > N_NODES) {
        for (int i = tid; i < 64 * 36; i += 256) {
            ((uint32_t*)sA)[i] = 0;
            ((uint32_t*)sM)[i] = 0;
        }
    }
    __syncthreads();

    // gather phase: warp handles rows [wid*8, wid*8+8)
    const float2* egoA2 = (const float2*)g_egoA;
    for (int rr = 0; rr < 8; rr++) {
        int lrow = wid * 8 + rr;
        int r = rbase + lrow;
        if (r < N_NODES) {
            float ax = 0.f, ay = 0.f;
            gather_row(g_egoAh, lane, g_off[r], g_off[r + 1], ax, ay);
            float2 eg = egoA2[r * 32 + lane];
            *(__half2*)&sA[lrow * 72 + 2 * lane] = __floats2half2_rn(eg.x + ax, eg.y + ay);
            *(__half2*)&sM[lrow * 72 + 2 * lane] = __floats2half2_rn(eg.x * ax, eg.y * ay);
        }
    }
    __syncthreads();

    // mma phase
    int t = wid >> 1;
    int h = wid & 1;

    float d1[16], d2[16];
    #pragma unroll
    for (int nt = 0; nt < 4; nt++) {
        int c = h * 32 + nt * 8 + (lane & 3) * 2;
        float bb1a = b1[c], bb1b = b1[c + 1];
        float bb2a = b2[c], bb2b = b2[c + 1];
        d1[nt * 4 + 0] = bb1a; d1[nt * 4 + 1] = bb1b;
        d1[nt * 4 + 2] = bb1a; d1[nt * 4 + 3] = bb1b;
        d2[nt * 4 + 0] = bb2a; d2[nt * 4 + 1] = bb2b;
        d2[nt * 4 + 2] = bb2a; d2[nt * 4 + 3] = bb2b;
    }

    int q = lane >> 3;
    int ri = lane & 7;
    int arow = t * 16 + (q & 1) * 8 + ri;
    int acol = (q >> 1) * 8;
    uint32_t aA = smem_u32(&sA[arow * 72 + acol]);
    uint32_t aM = smem_u32(&sM[arow * 72 + acol]);
    int g2 = q & 1;
    uint32_t bW1 = smem_u32(&sW1[(g2 * 8 + ri) * 72 + h * 32]);
    uint32_t bW2 = smem_u32(&sW2[(g2 * 8 + ri) * 72 + h * 32]);

    #pragma unroll
    for (int ks = 0; ks < 4; ks++) {
        uint32_t a0, a1, a2, a3;
        LDSM_X4(a0, a1, a2, a3, aA + ks * 32);           // +16 halves per kstep
        #pragma unroll
        for (int nt = 0; nt < 4; nt++) {
            uint32_t b0, b1r;
            LDSM_X2T(b0, b1r, bW1 + ks * 16 * 144 + nt * 16);
            MMA16816(&d1[nt * 4], a0, a1, a2, a3, b0, b1r);
        }
        LDSM_X4(a0, a1, a2, a3, aM + ks * 32);
        #pragma unroll
        for (int nt = 0; nt < 4; nt++) {
            uint32_t b0, b1r;
            LDSM_X2T(b0, b1r, bW2 + ks * 16 * 144 + nt * 16);
            MMA16816(&d2[nt * 4], a0, a1, a2, a3, b0, b1r);
        }
    }

    // epilogue: h = lrelu(d1) + lrelu(d2); l2norm per row
    float ss0 = 0.f, ss1 = 0.f;
    #pragma unroll
    for (int nt = 0; nt < 4; nt++) {
        #pragma unroll
        for (int i = 0; i < 4; i++) {
            float v1 = d1[nt * 4 + i], v2 = d2[nt * 4 + i];
            float v = (v1 > 0.f ? v1 : 0.01f * v1) + (v2 > 0.f ? v2 : 0.01f * v2);
            d1[nt * 4 + i] = v;
            if (i < 2) ss0 += v * v; else ss1 += v * v;
        }
    }
    ss0 += __shfl_xor_sync(0xFFFFFFFFu, ss0, 1);
    ss0 += __shfl_xor_sync(0xFFFFFFFFu, ss0, 2);
    ss1 += __shfl_xor_sync(0xFFFFFFFFu, ss1, 1);
    ss1 += __shfl_xor_sync(0xFFFFFFFFu, ss1, 2);
    if ((lane & 3) == 0) {
        sP[t * 16 + (lane >> 2)][h] = ss0;
        sP[t * 16 + (lane >> 2) + 8][h] = ss1;
    }
    __syncthreads();

    int r0 = t * 16 + (lane >> 2);
    int r1 = r0 + 8;
    float inv0 = 1.f / fmaxf(sqrtf(sP[r0][0] + sP[r0][1]), 1e-12f);
    float inv1 = 1.f / fmaxf(sqrtf(sP[r1][0] + sP[r1][1]), 1e-12f);
    int gr0 = rbase + r0, gr1 = rbase + r1;
    #pragma unroll
    for (int nt = 0; nt < 4; nt++) {
        int c = h * 32 + nt * 8 + (lane & 3) * 2;
        if (gr0 < N_NODES) {
            float x0 = d1[nt * 4 + 0] * inv0, x1 = d1[nt * 4 + 1] * inv0;
            *(float2*)&out[gr0 * 160 + 64 + c] = make_float2(x0, x1);
            g_egoB[gr0 * 32 + (c >> 1)] = make_float2(x0, x1);
            g_egoBh[gr0 * 32 + (c >> 1)] = __floats2half2_rn(x0, x1);
        }
        if (gr1 < N_NODES) {
            float x0 = d1[nt * 4 + 2] * inv1, x1 = d1[nt * 4 + 3] * inv1;
            *(float2*)&out[gr1 * 160 + 64 + c] = make_float2(x0, x1);
            g_egoB[gr1 * 32 + (c >> 1)] = make_float2(x0, x1);
            g_egoBh[gr1 * 32 + (c >> 1)] = __floats2half2_rn(x0, x1);
        }
    }
}

// ---------------------------------------------------------------------------
// Fused layer 2: same structure, N=32. Warp (t, h) computes D[16, 16].
// ---------------------------------------------------------------------------
__global__ __launch_bounds__(256) void k_layer2(
    const float* __restrict__ W1, const float* __restrict__ b1,
    const float* __restrict__ W2, const float* __restrict__ b2,
    float* __restrict__ out)
{
    __shared__ __align__(16) __half sA[64 * 72];
    __shared__ __align__(16) __half sM[64 * 72];
    __shared__ __align__(16) __half sW1[64 * 40];
    __shared__ __align__(16) __half sW2[64 * 40];
    __shared__ float sP[64][2];

    int tid = threadIdx.x;
    int wid = tid >> 5;
    int lane = tid & 31;
    int rbase = blockIdx.x * 64;

    for (int i = tid; i < 2048; i += 256) {
        int k = i >> 5, n = i & 31;
        sW1[k * 40 + n] = __float2half(W1[i]);
        sW2[k * 40 + n] = __float2half(W2[i]);
    }
    if (rbase + 64 > N_NODES) {
        for (int i = tid; i < 64 * 36; i += 256) {
            ((uint32_t*)sA)[i] = 0;
            ((uint32_t*)sM)[i] = 0;
        }
    }
    __syncthreads();

    for (int rr = 0; rr < 8; rr++) {
        int lrow = wid * 8 + rr;
        int r = rbase + lrow;
        if (r < N_NODES) {
            float ax = 0.f, ay = 0.f;
            gather_row(g_egoBh, lane, g_off[r], g_off[r + 1], ax, ay);
            float2 eg = g_egoB[r * 32 + lane];
            *(__half2*)&sA[lrow * 72 + 2 * lane] = __floats2half2_rn(eg.x + ax, eg.y + ay);
            *(__half2*)&sM[lrow * 72 + 2 * lane] = __floats2half2_rn(eg.x * ax, eg.y * ay);
        }
    }
    __syncthreads();

    int t = wid >> 1;
    int h = wid & 1;

    float d1[8], d2[8];
    #pragma unroll
    for (int nt = 0; nt < 2; nt++) {
        int c = h * 16 + nt * 8 + (lane & 3) * 2;
        float bb1a = b1[c], bb1b = b1[c + 1];
        float bb2a = b2[c], bb2b = b2[c + 1];
        d1[nt * 4 + 0] = bb1a; d1[nt * 4 + 1] = bb1b;
        d1[nt * 4 + 2] = bb1a; d1[nt * 4 + 3] = bb1b;
        d2[nt * 4 + 0] = bb2a; d2[nt * 4 + 1] = bb2b;
        d2[nt * 4 + 2] = bb2a; d2[nt * 4 + 3] = bb2b;
    }

    int q = lane >> 3;
    int ri = lane & 7;
    int arow = t * 16 + (q & 1) * 8 + ri;
    int acol = (q >> 1) * 8;
    uint32_t aA = smem_u32(&sA[arow * 72 + acol]);
    uint32_t aM = smem_u32(&sM[arow * 72 + acol]);
    int g2 = q & 1;
    uint32_t bW1 = smem_u32(&sW1[(g2 * 8 + ri) * 40 + h * 16]);
    uint32_t bW2 = smem_u32(&sW2[(g2 * 8 + ri) * 40 + h * 16]);

    #pragma unroll
    for (int ks = 0; ks < 4; ks++) {
        uint32_t a0, a1, a2, a3;
        LDSM_X4(a0, a1, a2, a3, aA + ks * 32);
        #pragma unroll
        for (int nt = 0; nt < 2; nt++) {
            uint32_t b0, b1r;
            LDSM_X2T(b0, b1r, bW1 + ks * 16 * 80 + nt * 16);
            MMA16816(&d1[nt * 4], a0, a1, a2, a3, b0, b1r);
        }
        LDSM_X4(a0, a1, a2, a3, aM + ks * 32);
        #pragma unroll
        for (int nt = 0; nt < 2; nt++) {
            uint32_t b0, b1r;
            LDSM_X2T(b0, b1r, bW2 + ks * 16 * 80 + nt * 16);
            MMA16816(&d2[nt * 4], a0, a1, a2, a3, b0, b1r);
        }
    }

    float ss0 = 0.f, ss1 = 0.f;
    #pragma unroll
    for (int nt = 0; nt < 2; nt++) {
        #pragma unroll
        for (int i = 0; i < 4; i++) {
            float v1 = d1[nt * 4 + i], v2 = d2[nt * 4 + i];
            float v = (v1 > 0.f ? v1 : 0.01f * v1) + (v2 > 0.f ? v2 : 0.01f * v2);
            d1[nt * 4 + i] = v;
            if (i < 2) ss0 += v * v; else ss1 += v * v;
        }
    }
    ss0 += __shfl_xor_sync(0xFFFFFFFFu, ss0, 1);
    ss0 += __shfl_xor_sync(0xFFFFFFFFu, ss0, 2);
    ss1 += __shfl_xor_sync(0xFFFFFFFFu, ss1, 1);
    ss1 += __shfl_xor_sync(0xFFFFFFFFu, ss1, 2);
    if ((lane & 3) == 0) {
        sP[t * 16 + (lane >> 2)][h] = ss0;
        sP[t * 16 + (lane >> 2) + 8][h] = ss1;
    }
    __syncthreads();

    int r0 = t * 16 + (lane >> 2);
    int r1 = r0 + 8;
    float inv0 = 1.f / fmaxf(sqrtf(sP[r0][0] + sP[r0][1]), 1e-12f);
    float inv1 = 1.f / fmaxf(sqrtf(sP[r1][0] + sP[r1][1]), 1e-12f);
    int gr0 = rbase + r0, gr1 = rbase + r1;
    #pragma unroll
    for (int nt = 0; nt < 2; nt++) {
        int c = h * 16 + nt * 8 + (lane & 3) * 2;
        if (gr0 < N_NODES) {
            *(float2*)&out[gr0 * 160 + 128 + c] =
                make_float2(d1[nt * 4 + 0] * inv0, d1[nt * 4 + 1] * inv0);
        }
        if (gr1 < N_NODES) {
            *(float2*)&out[gr1 * 160 + 128 + c] =
                make_float2(d1[nt * 4 + 2] * inv1, d1[nt * 4 + 3] * inv1);
        }
    }
}

// ---------------------------------------------------------------------------
extern "C" void kernel_launch(void* const* d_in, const int* in_sizes, int n_in,
                              void* d_out, int out_size)
{
    const float* user_tab = (const float*)d_in[0];
    const float* entity_tab = (const float*)d_in[1];
    const float* A_vals = (const float*)d_in[2];
    const float* W1_1 = (const float*)d_in[3];
    const float* b1_1 = (const float*)d_in[4];
    const float* W2_1 = (const float*)d_in[5];
    const float* b2_1 = (const float*)d_in[6];
    const float* W1_2 = (const float*)d_in[7];
    const float* b1_2 = (const float*)d_in[8];
    const float* W2_2 = (const float*)d_in[9];
    const float* b2_2 = (const float*)d_in[10];
    const int* A_rows = (const int*)d_in[11];
    const int* A_cols = (const int*)d_in[12];
    float* out = (float*)d_out;

    int eg = (N_EDGES + 255) / 256;

    void* cnt_ptr = nullptr;
    cudaGetSymbolAddress(&cnt_ptr, g_cnt);
    cudaMemsetAsync(cnt_ptr, 0, N_NODES * sizeof(int));
    void* st_ptr = nullptr;
    cudaGetSymbolAddress(&st_ptr, g_state);
    cudaMemsetAsync(st_ptr, 0, SCAN_NB * sizeof(ull));

    // 0: init
    k_init<<<(N_NODES * 16 + 255) / 256, 256>>>(
        (const float4*)user_tab, (const float4*)entity_tab, A_rows, (float4*)out);
    // 1: scan
    k_scan<<<SCAN_NB, SCAN_BS>>>();
    // 2: scatter
    k_scatter<<<eg, 256>>>(A_rows, A_cols, A_vals);
    // 3: fused layer 1 (tensor-core GEMM)
    k_layer1<<<(N_NODES + 63) / 64, 256>>>(W1_1, b1_1, W2_1, b2_1, out);
    // 4: fused layer 2
    k_layer2<<<(N_NODES + 63) / 64, 256>>>(W1_2, b1_2, W2_2, b2_2, out);
}